// round 2
// baseline (speedup 1.0000x reference)
#include <cuda_runtime.h>

#define NN 50000
#define EE 800000
#define BB 2
#define TT 12
#define T2 10   // after TC1
#define T3 8    // after TC2
#define HH 16
#define ROW (BB*T2*HH)   // 320 floats per node for h1/agg/h2
#define CLS 2

// ---------------- device scratch (static: no allocations allowed) ------------
__device__ int   g_is64;
__device__ float g_deg[NN];
__device__ float g_dis[NN];
__device__ int   g_cnt[NN];
__device__ int   g_rowptr[NN + 1];
__device__ int   g_woff[NN];
__device__ int   g_csr_src[EE];
__device__ float g_csr_norm[EE];
__device__ float g_h1[NN * ROW];    // 64 MB, (n, b, t, h)
__device__ float g_agg[NN * ROW];   // 64 MB
__device__ float g_h2[NN * ROW];    // 64 MB

__device__ __forceinline__ int edge_val(const void* ei, int which, int e, int is64) {
    if (is64) return (int)((const long long*)ei)[(long long)which * EE + e];
    return ((const int*)ei)[which * EE + e];
}

// ---------------- dtype detect (int32 vs int64 edge_index) ----------------
__global__ void k_detect(const void* ei) {
    // If buffer is int64 (LE), odd int32 words are the high halves -> all 0
    // for values in [0, 50000). With int32 data, odd words are real indices;
    // P(all 64 sampled are 0) ~ 0.
    const int* p = (const int*)ei;
    int nz = 0;
    for (int i = 0; i < 64; i++) nz |= p[2 * i + 1];
    g_is64 = (nz == 0) ? 1 : 0;
}

// ---------------- CSR build ----------------
__global__ void k_zero() {
    int i = blockIdx.x * blockDim.x + threadIdx.x;
    if (i < NN) { g_deg[i] = 0.f; g_cnt[i] = 0; }
}

__global__ void k_hist(const void* __restrict__ ei, const float* __restrict__ ew) {
    int e = blockIdx.x * blockDim.x + threadIdx.x;
    int is64 = g_is64;
    if (e < EE) {
        int s = edge_val(ei, 0, e, is64);
        int d = edge_val(ei, 1, e, is64);
        atomicAdd(&g_deg[s], ew[e]);
        atomicAdd(&g_cnt[d], 1);
    }
}

__global__ void k_dis() {
    int i = blockIdx.x * blockDim.x + threadIdx.x;
    if (i < NN) {
        float dg = g_deg[i];
        g_dis[i] = (dg > 0.f) ? rsqrtf(fmaxf(dg, 1e-12f)) : 0.f;
    }
}

// single-block exclusive scan of g_cnt -> g_rowptr / g_woff
__global__ void k_scan() {
    __shared__ int ss[1024];
    const int CH = (NN + 1023) / 1024;  // 49
    int t = threadIdx.x;
    int lo = t * CH;
    int hi = lo + CH; if (hi > NN) hi = NN;
    int s = 0;
    for (int i = lo; i < hi; i++) s += g_cnt[i];
    ss[t] = s;
    __syncthreads();
    for (int off = 1; off < 1024; off <<= 1) {
        int v = (t >= off) ? ss[t - off] : 0;
        __syncthreads();
        ss[t] += v;
        __syncthreads();
    }
    int run = (t == 0) ? 0 : ss[t - 1];
    for (int i = lo; i < hi; i++) {
        int c = g_cnt[i];
        g_rowptr[i] = run;
        g_woff[i]   = run;
        run += c;
    }
    if (t == 1023) g_rowptr[NN] = ss[1023];
}

__global__ void k_scatter(const void* __restrict__ ei, const float* __restrict__ ew) {
    int e = blockIdx.x * blockDim.x + threadIdx.x;
    int is64 = g_is64;
    if (e < EE) {
        int s = edge_val(ei, 0, e, is64);
        int d = edge_val(ei, 1, e, is64);
        float nm = -g_dis[s] * ew[e] * g_dis[d];
        int pos = atomicAdd(&g_woff[d], 1);
        g_csr_src[pos]  = s;
        g_csr_norm[pos] = nm;
    }
}

// ---------------- TC1: (B,T,N,1) -> h1 (n-major (n,b,t,h)) ----------------
__global__ void k_tc1(const float* __restrict__ x,
                      const float* __restrict__ wP, const float* __restrict__ bP,
                      const float* __restrict__ wQ, const float* __restrict__ bQ,
                      const float* __restrict__ wR, const float* __restrict__ bR) {
    __shared__ float sw[192];  // P(48) Q(48) R(48) bP(16) bQ(16) bR(16)
    int tid = threadIdx.x;
    if (tid < 48)       sw[tid] = wP[tid];
    else if (tid < 96)  sw[tid] = wQ[tid - 48];
    else if (tid < 144) sw[tid] = wR[tid - 96];
    else if (tid < 160) sw[tid] = bP[tid - 144];
    else if (tid < 176) sw[tid] = bQ[tid - 160];
    else if (tid < 192) sw[tid] = bR[tid - 176];
    __syncthreads();

    int g = blockIdx.x * blockDim.x + tid;
    if (g >= BB * T2 * NN) return;
    int n  = g % NN;
    int bt = g / NN;             // b*T2 + t
    int b  = bt / T2;
    int t  = bt % T2;

    float xv0 = x[(b * TT + t    ) * NN + n];
    float xv1 = x[(b * TT + t + 1) * NN + n];
    float xv2 = x[(b * TT + t + 2) * NN + n];

    float out[16];
#pragma unroll
    for (int h = 0; h < 16; h++) {
        float p = sw[144 + h] + xv0 * sw[h]      + xv1 * sw[16 + h]  + xv2 * sw[32 + h];
        float q = sw[160 + h] + xv0 * sw[48 + h] + xv1 * sw[64 + h]  + xv2 * sw[80 + h];
        float r = sw[176 + h] + xv0 * sw[96 + h] + xv1 * sw[112 + h] + xv2 * sw[128 + h];
        float sg = 1.f / (1.f + __expf(-q));
        float v  = p * sg + r;
        out[h] = (v > 0.f) ? v : 0.f;
    }
    float4* dst = (float4*)&g_h1[n * ROW + bt * 16];
#pragma unroll
    for (int j = 0; j < 4; j++)
        dst[j] = make_float4(out[4*j], out[4*j+1], out[4*j+2], out[4*j+3]);
}

// ---------------- gather: one warp per dst node, 10 accumulators ------------
__global__ void k_gather() {
    int warp = (blockIdx.x * blockDim.x + threadIdx.x) >> 5;
    int lane = threadIdx.x & 31;
    if (warp >= NN) return;
    int d   = warp;
    int beg = g_rowptr[d];
    int end = g_rowptr[d + 1];

    float acc[10];
#pragma unroll
    for (int j = 0; j < 10; j++) acc[j] = 0.f;

    for (int i = beg; i < end; i++) {
        int   s  = g_csr_src[i];
        float nm = g_csr_norm[i];
        const float* p = &g_h1[s * ROW + lane];
#pragma unroll
        for (int j = 0; j < 10; j++) acc[j] += nm * p[j * 32];
    }
    float* q = &g_agg[d * ROW + lane];
#pragma unroll
    for (int j = 0; j < 10; j++) q[j * 32] = acc[j];
}

// ---------------- cheb combine: h2 = relu(h1@W0 + agg@W1 + b) ---------------
__global__ void k_cheb(const float* __restrict__ w, const float* __restrict__ bias) {
    __shared__ float sw0[256], sw1[256], sb[16];
    int tid = threadIdx.x;
    if (tid < 256) { sw0[tid] = w[tid]; sw1[tid] = w[256 + tid]; }
    if (tid < 16)  sb[tid] = bias[tid];
    __syncthreads();

    int g = blockIdx.x * blockDim.x + tid;  // g = n*20 + bt
    if (g >= NN * (BB * T2)) return;
    int off = g * 16;  // n*320 + bt*16

    float xv[16], av[16];
    const float4* xp = (const float4*)&g_h1[off];
    const float4* ap = (const float4*)&g_agg[off];
#pragma unroll
    for (int j = 0; j < 4; j++) {
        float4 v = xp[j];
        xv[4*j] = v.x; xv[4*j+1] = v.y; xv[4*j+2] = v.z; xv[4*j+3] = v.w;
        float4 a = ap[j];
        av[4*j] = a.x; av[4*j+1] = a.y; av[4*j+2] = a.z; av[4*j+3] = a.w;
    }
    float acc[16];
#pragma unroll
    for (int h = 0; h < 16; h++) acc[h] = sb[h];
#pragma unroll
    for (int c = 0; c < 16; c++) {
        float xc = xv[c], ac = av[c];
#pragma unroll
        for (int h = 0; h < 16; h++)
            acc[h] += xc * sw0[c * 16 + h] + ac * sw1[c * 16 + h];
    }
    float4* dst = (float4*)&g_h2[off];
#pragma unroll
    for (int j = 0; j < 4; j++) {
        float a0 = acc[4*j],   a1 = acc[4*j+1], a2 = acc[4*j+2], a3 = acc[4*j+3];
        dst[j] = make_float4(a0 > 0.f ? a0 : 0.f, a1 > 0.f ? a1 : 0.f,
                             a2 > 0.f ? a2 : 0.f, a3 > 0.f ? a3 : 0.f);
    }
}

// ---------------- TC2 + mean over t' + linear -> out (B,N,2) ----------------
#define SXSTRIDE 168
__global__ void k_tc2(const float* __restrict__ wP, const float* __restrict__ bP,
                      const float* __restrict__ wQ, const float* __restrict__ bQ,
                      const float* __restrict__ wR, const float* __restrict__ bR,
                      const float* __restrict__ lw, const float* __restrict__ lb,
                      float* __restrict__ out) {
    __shared__ float sx[16 * SXSTRIDE];           // 16 (n,b) rows of 160, padded
    __shared__ float swP[768], swQ[768], swR[768];
    __shared__ float sbP[16], sbQ[16], sbR[16], slw[32], slb[2];
    int tid = threadIdx.x;
    for (int i = tid; i < 768; i += 256) { swP[i] = wP[i]; swQ[i] = wQ[i]; swR[i] = wR[i]; }
    if (tid < 16) { sbP[tid] = bP[tid]; sbQ[tid] = bQ[tid]; sbR[tid] = bR[tid]; }
    if (tid < 32) slw[tid] = lw[tid];
    if (tid < 2)  slb[tid] = lb[tid];

    int pair0 = blockIdx.x * 16;                  // pair = n*2 + b
    const float* src = &g_h2[pair0 * (T2 * HH)];  // 16 rows * 160 contiguous
    for (int i = tid; i < 16 * T2 * HH; i += 256) {
        int r = i / (T2 * HH), c = i % (T2 * HH);
        sx[r * SXSTRIDE + c] = src[i];
    }
    __syncthreads();

    int gloc = tid >> 4;      // local pair 0..15
    int h    = tid & 15;
    const float* xs = &sx[gloc * SXSTRIDE];

    float accP[T3], accQ[T3], accR[T3];
#pragma unroll
    for (int tp = 0; tp < T3; tp++) { accP[tp] = sbP[h]; accQ[tp] = sbQ[h]; accR[tp] = sbR[h]; }

#pragma unroll
    for (int c = 0; c < 16; c++) {
        float xr[T2];
#pragma unroll
        for (int t = 0; t < T2; t++) xr[t] = xs[t * 16 + c];
#pragma unroll
        for (int k = 0; k < 3; k++) {
            float wp = swP[k * 256 + c * 16 + h];
            float wq = swQ[k * 256 + c * 16 + h];
            float wr = swR[k * 256 + c * 16 + h];
#pragma unroll
            for (int tp = 0; tp < T3; tp++) {
                float xvv = xr[tp + k];
                accP[tp] += xvv * wp;
                accQ[tp] += xvv * wq;
                accR[tp] += xvv * wr;
            }
        }
    }

    float ms = 0.f;
#pragma unroll
    for (int tp = 0; tp < T3; tp++) {
        float sg = 1.f / (1.f + __expf(-accQ[tp]));
        float v  = accP[tp] * sg + accR[tp];
        ms += (v > 0.f) ? v : 0.f;
    }
    ms *= (1.f / (float)T3);

    float c0 = ms * slw[h * 2 + 0];
    float c1 = ms * slw[h * 2 + 1];
#pragma unroll
    for (int o = 8; o >= 1; o >>= 1) {
        c0 += __shfl_xor_sync(0xffffffffu, c0, o);
        c1 += __shfl_xor_sync(0xffffffffu, c1, o);
    }
    if (h == 0) {
        int pair = pair0 + gloc;
        int n = pair >> 1, b = pair & 1;
        out[(b * NN + n) * CLS + 0] = c0 + slb[0];
        out[(b * NN + n) * CLS + 1] = c1 + slb[1];
    }
}

// ---------------- launch ----------------
extern "C" void kernel_launch(void* const* d_in, const int* in_sizes, int n_in,
                              void* d_out, int out_size) {
    const float* x  = (const float*)d_in[0];
    const void*  ei = d_in[1];
    const float* ew = (const float*)d_in[2];

    // Detect ordering (dict order matches signature: tc1, tc2, cheb, lin;
    // fall back if cheb comes first). tc2_P_w has 768 elems, cheb_w 512.
    int i_tc1 = 3, i_tc2, i_cheb, i_lin;
    if (in_sizes[9] == 512) { i_cheb = 9; i_tc2 = 11; i_lin = 17; }
    else                    { i_tc2 = 9; i_cheb = 15; i_lin = 17; }

    const float* t1Pw = (const float*)d_in[i_tc1 + 0];
    const float* t1Pb = (const float*)d_in[i_tc1 + 1];
    const float* t1Qw = (const float*)d_in[i_tc1 + 2];
    const float* t1Qb = (const float*)d_in[i_tc1 + 3];
    const float* t1Rw = (const float*)d_in[i_tc1 + 4];
    const float* t1Rb = (const float*)d_in[i_tc1 + 5];
    const float* t2Pw = (const float*)d_in[i_tc2 + 0];
    const float* t2Pb = (const float*)d_in[i_tc2 + 1];
    const float* t2Qw = (const float*)d_in[i_tc2 + 2];
    const float* t2Qb = (const float*)d_in[i_tc2 + 3];
    const float* t2Rw = (const float*)d_in[i_tc2 + 4];
    const float* t2Rb = (const float*)d_in[i_tc2 + 5];
    const float* chw  = (const float*)d_in[i_cheb + 0];
    const float* chb  = (const float*)d_in[i_cheb + 1];
    const float* lw   = (const float*)d_in[i_lin + 0];
    const float* lb   = (const float*)d_in[i_lin + 1];
    float* out = (float*)d_out;

    const int TB = 256;
    // dtype detect + CSR prep
    k_detect<<<1, 1>>>(ei);
    k_zero<<<(NN + TB - 1) / TB, TB>>>();
    k_hist<<<(EE + TB - 1) / TB, TB>>>(ei, ew);
    k_dis<<<(NN + TB - 1) / TB, TB>>>();
    k_scan<<<1, 1024>>>();
    k_scatter<<<(EE + TB - 1) / TB, TB>>>(ei, ew);
    // TC1
    k_tc1<<<(BB * T2 * NN + TB - 1) / TB, TB>>>(x, t1Pw, t1Pb, t1Qw, t1Qb, t1Rw, t1Rb);
    // Cheb aggregate + combine
    k_gather<<<(NN * 32 + TB - 1) / TB, TB>>>();
    k_cheb<<<(NN * BB * T2 + TB - 1) / TB, TB>>>(chw, chb);
    // TC2 + mean + linear
    k_tc2<<<(NN * BB) / 16, TB>>>(t2Pw, t2Pb, t2Qw, t2Qb, t2Rw, t2Rb, lw, lb, out);
}